// round 16
// baseline (speedup 1.0000x reference)
#include <cuda_runtime.h>
#include <math.h>

#define N_CLASSES 1000
#define L4        250          // label row in float4s (1000/4)
#define EMBED     1024
#define THREADS   128
#define WPB       4            // warps (rows) per block
#define GRID      8192         // 32768 / WPB

__global__ void __launch_bounds__(THREADS, 1)
angular_loss_kernel(const float* __restrict__ features,
                    const float* __restrict__ labels,
                    const float* __restrict__ mean_class,
                    float* __restrict__ out,
                    int N)
{
    const int warp = threadIdx.x >> 5;
    const int lane = threadIdx.x & 31;
    const int row  = blockIdx.x * WPB + warp;

    __shared__ float s_part[WPB];

    const float4* lrow = reinterpret_cast<const float4*>(
        labels + (size_t)row * N_CLASSES);
    const float4* frow = reinterpret_cast<const float4*>(
        features + (size_t)row * EMBED);

    // ---- front-batch both DRAM streams, interleaved (16 loads in flight).
    //      Pinned by R4/R6/R7/R8: one unbroken issue burst is worth more
    //      than any byte-saving or occupancy-raising alternative.
    float4 lv[8], fv[8];
    #pragma unroll
    for (int k = 0; k < 8; k++) {
        const int idx = k * 32 + lane;
        lv[k] = (idx < L4) ? __ldcs(&lrow[idx]) : make_float4(0.f, 0.f, 0.f, 0.f);
        fv[k] = __ldcs(&frow[idx]);
    }

    // ---- resolve the one-hot (c, v) for this row ----
    int   c_loc = -1;
    float v_loc = 0.0f;
    #pragma unroll
    for (int k = 0; k < 8; k++) {
        const int base = (k * 32 + lane) * 4;
        if (lv[k].x != 0.0f) { c_loc = base + 0; v_loc = lv[k].x; }
        if (lv[k].y != 0.0f) { c_loc = base + 1; v_loc = lv[k].y; }
        if (lv[k].z != 0.0f) { c_loc = base + 2; v_loc = lv[k].z; }
        if (lv[k].w != 0.0f) { c_loc = base + 3; v_loc = lv[k].w; }
    }
    const unsigned found = __ballot_sync(0xFFFFFFFFu, c_loc >= 0);
    const int src = found ? (__ffs(found) - 1) : 0;
    int   c = __shfl_sync(0xFFFFFFFFu, c_loc, src);
    float v = __shfl_sync(0xFFFFFFFFu, v_loc, src);
    if (c < 0) { c = 0; v = 0.0f; }

    // ---- gather mean_class[c] (L2-hot, 4 MB table) and reduce ----
    const float4* mrow = reinterpret_cast<const float4*>(
        mean_class + (size_t)c * EMBED);
    float4 mv[8];
    #pragma unroll
    for (int k = 0; k < 8; k++) mv[k] = __ldg(&mrow[k * 32 + lane]);

    float ff = 0.0f, pp = 0.0f, fp = 0.0f;
    #pragma unroll
    for (int k = 0; k < 8; k++) {
        const float4 f = fv[k];
        const float4 m = mv[k];
        ff += f.x*f.x + f.y*f.y + f.z*f.z + f.w*f.w;
        pp += m.x*m.x + m.y*m.y + m.z*m.z + m.w*m.w;
        fp += f.x*m.x + f.y*m.y + f.z*m.z + f.w*m.w;
    }
    #pragma unroll
    for (int off = 16; off > 0; off >>= 1) {
        ff += __shfl_xor_sync(0xFFFFFFFFu, ff, off);
        pp += __shfl_xor_sync(0xFFFFFFFFu, pp, off);
        fp += __shfl_xor_sync(0xFFFFFFFFu, fp, off);
    }

    if (lane == 0) {
        const float eps = 1e-12f;
        const float nf   = fmaxf(sqrtf(ff), eps);
        const float np   = fmaxf(fabsf(v) * sqrtf(pp), eps);
        const float cosv = (v * fp) / (nf * np);
        s_part[warp] = 1.0f - cosv;
    }
    __syncthreads();

    // ---- block-aggregated atomic: 1 per CTA (load-bearing, see R13) ----
    if (threadIdx.x == 0) {
        float s = (s_part[0] + s_part[1]) + (s_part[2] + s_part[3]);
        atomicAdd(out, s / (float)N);
    }
}

extern "C" void kernel_launch(void* const* d_in, const int* in_sizes, int n_in,
                              void* d_out, int out_size)
{
    const float* features   = (const float*)d_in[0];
    const float* labels     = (const float*)d_in[1];
    const float* mean_class = (const float*)d_in[2];
    float* out = (float*)d_out;

    const int N = in_sizes[0] / EMBED;   // 32768

    cudaMemsetAsync(out, 0, sizeof(float));   // graph-capturable memset node
    angular_loss_kernel<<<GRID, THREADS>>>(
        features, labels, mean_class, out, N);
}

// round 17
// speedup vs baseline: 1.0089x; 1.0089x over previous
#include <cuda_runtime.h>
#include <math.h>

#define N_CLASSES 1000
#define L4        250          // label row in float4s (1000/4)
#define EMBED     1024
#define THREADS   128
#define WPB       4            // warps (rows) per block
#define GRID      8192         // 32768 / WPB

__global__ void __launch_bounds__(THREADS, 1)
angular_loss_kernel(const float* __restrict__ features,
                    const float* __restrict__ labels,
                    const float* __restrict__ mean_class,
                    float* __restrict__ out,
                    int N)
{
    const int warp = threadIdx.x >> 5;
    const int lane = threadIdx.x & 31;
    const int row  = blockIdx.x * WPB + warp;

    __shared__ float s_part[WPB];

    const float4* lrow = reinterpret_cast<const float4*>(
        labels + (size_t)row * N_CLASSES);
    const float4* frow = reinterpret_cast<const float4*>(
        features + (size_t)row * EMBED);

    // ---- front-batch both DRAM streams, interleaved (16 loads in flight).
    //      Pinned by R4/R6/R7/R8: one unbroken issue burst is worth more
    //      than any byte-saving or occupancy-raising alternative.
    float4 lv[8], fv[8];
    #pragma unroll
    for (int k = 0; k < 8; k++) {
        const int idx = k * 32 + lane;
        lv[k] = (idx < L4) ? __ldcs(&lrow[idx]) : make_float4(0.f, 0.f, 0.f, 0.f);
        fv[k] = __ldcs(&frow[idx]);
    }

    // ---- resolve the one-hot (c, v) for this row ----
    int   c_loc = -1;
    float v_loc = 0.0f;
    #pragma unroll
    for (int k = 0; k < 8; k++) {
        const int base = (k * 32 + lane) * 4;
        if (lv[k].x != 0.0f) { c_loc = base + 0; v_loc = lv[k].x; }
        if (lv[k].y != 0.0f) { c_loc = base + 1; v_loc = lv[k].y; }
        if (lv[k].z != 0.0f) { c_loc = base + 2; v_loc = lv[k].z; }
        if (lv[k].w != 0.0f) { c_loc = base + 3; v_loc = lv[k].w; }
    }
    const unsigned found = __ballot_sync(0xFFFFFFFFu, c_loc >= 0);
    const int src = found ? (__ffs(found) - 1) : 0;
    int   c = __shfl_sync(0xFFFFFFFFu, c_loc, src);
    float v = __shfl_sync(0xFFFFFFFFu, v_loc, src);
    if (c < 0) { c = 0; v = 0.0f; }

    // ---- gather mean_class[c] (L2-hot, 4 MB table) and reduce ----
    const float4* mrow = reinterpret_cast<const float4*>(
        mean_class + (size_t)c * EMBED);
    float4 mv[8];
    #pragma unroll
    for (int k = 0; k < 8; k++) mv[k] = __ldg(&mrow[k * 32 + lane]);

    float ff = 0.0f, pp = 0.0f, fp = 0.0f;
    #pragma unroll
    for (int k = 0; k < 8; k++) {
        const float4 f = fv[k];
        const float4 m = mv[k];
        ff += f.x*f.x + f.y*f.y + f.z*f.z + f.w*f.w;
        pp += m.x*m.x + m.y*m.y + m.z*m.z + m.w*m.w;
        fp += f.x*m.x + f.y*m.y + f.z*m.z + f.w*m.w;
    }
    #pragma unroll
    for (int off = 16; off > 0; off >>= 1) {
        ff += __shfl_xor_sync(0xFFFFFFFFu, ff, off);
        pp += __shfl_xor_sync(0xFFFFFFFFu, pp, off);
        fp += __shfl_xor_sync(0xFFFFFFFFu, fp, off);
    }

    if (lane == 0) {
        const float eps = 1e-12f;
        const float nf   = fmaxf(sqrtf(ff), eps);
        const float np   = fmaxf(fabsf(v) * sqrtf(pp), eps);
        const float cosv = (v * fp) / (nf * np);
        s_part[warp] = 1.0f - cosv;
    }
    __syncthreads();

    // ---- block-aggregated atomic: 1 per CTA (load-bearing, see R13) ----
    if (threadIdx.x == 0) {
        float s = (s_part[0] + s_part[1]) + (s_part[2] + s_part[3]);
        atomicAdd(out, s / (float)N);
    }
}

extern "C" void kernel_launch(void* const* d_in, const int* in_sizes, int n_in,
                              void* d_out, int out_size)
{
    const float* features   = (const float*)d_in[0];
    const float* labels     = (const float*)d_in[1];
    const float* mean_class = (const float*)d_in[2];
    float* out = (float*)d_out;

    const int N = in_sizes[0] / EMBED;   // 32768

    cudaMemsetAsync(out, 0, sizeof(float));   // graph-capturable memset node
    angular_loss_kernel<<<GRID, THREADS>>>(
        features, labels, mean_class, out, N);
}